// round 4
// baseline (speedup 1.0000x reference)
#include <cuda_runtime.h>
#include <cuda_bf16.h>
#include <math.h>

// ============================================================================
// PredictiveReasoningBlock fused kernel. One CTA per batch element.
// Shapes: B=4096, D=32, T=9, L=24, H=8, HD=4.
// ============================================================================

#define NTHR 256

// batch-invariant precomputed terms
__device__ float gA32[1024];    // 0.9*softplus(W_causal)*(1-I), row-normalized
__device__ float gBmixr[376];   // sum_h W_logit[h,Ho]*rel_pos_bias[h,r]  (8 x 47)

__device__ __forceinline__ float geluf(float x) {
    return 0.5f * x * (1.0f + erff(x * 0.7071067811865476f));
}
__device__ __forceinline__ float sigmoidf_(float x) {
    return 1.0f / (1.0f + __expf(-x));
}

__global__ void prb_precompute(const float* __restrict__ Wc,
                               const float* __restrict__ WL,
                               const float* __restrict__ rpb) {
    int tid = threadIdx.x;
    if (tid < 32) {
        float a[32];
        float rs = 0.f;
#pragma unroll
        for (int j = 0; j < 32; ++j) {
            float w = Wc[tid * 32 + j];
            float sp = (w > 20.f) ? w : log1pf(expf(w));
            if (j == tid) sp = 0.f;
            a[j] = sp;
            rs += sp;
        }
        float inv = 0.9f / (rs + 1e-6f);
#pragma unroll
        for (int j = 0; j < 32; ++j) gA32[tid * 32 + j] = a[j] * inv;
    }
    for (int idx = tid; idx < 376; idx += blockDim.x) {
        int Ho = idx / 47, r = idx % 47;
        float s = 0.f;
#pragma unroll
        for (int h = 0; h < 8; ++h) s += WL[h * 8 + Ho] * rpb[h * 47 + r];
        gBmixr[idx] = s;
    }
}

// ---------------------------------------------------------------------------
// shared memory layout (floats); total 27048 floats = 108192 bytes
// ---------------------------------------------------------------------------
// fs   [216][33]        0     : fused tile [tl][c], later overwritten by x_att
// ovl  overlay region   7128  : qn/kn/vn [24][36] + smx/smx2 [8][24][25]
//                               (also: stats partials early; conv wT [288][33];
//                                pwT[24][25] + p2[32][25] late)
// wq/wk/wv/wm [32][33]  19320 : transposed projection weights
// biases, A32[32][33], W_logit/W_ctx, bmixr, per-channel vectors,
// p1[32][25], pre_prompt[32][24], p_b, conv_b

__global__ __launch_bounds__(NTHR, 2)
void prb_kernel(const float* __restrict__ x,
                const float* __restrict__ ln_g,  const float* __restrict__ ln_b,
                const float* __restrict__ rp_w1, const float* __restrict__ rp_b1,
                const float* __restrict__ rp_w2, const float* __restrict__ rp_b2,
                const float* __restrict__ mask_w, const float* __restrict__ mask_b,
                const float* __restrict__ val_w1, const float* __restrict__ val_b1,
                const float* __restrict__ val_w2, const float* __restrict__ val_b2,
                const float* __restrict__ fuse_gate,
                const float* __restrict__ q_w, const float* __restrict__ q_b,
                const float* __restrict__ k_w, const float* __restrict__ k_b,
                const float* __restrict__ v_w, const float* __restrict__ v_b,
                const float* __restrict__ m_w, const float* __restrict__ m_b,
                const float* __restrict__ W_logit, const float* __restrict__ W_ctx,
                const float* __restrict__ pre_prompt,
                const float* __restrict__ conv_w, const float* __restrict__ conv_b,
                const float* __restrict__ p_w,   const float* __restrict__ p_b,
                float* __restrict__ out)
{
    extern __shared__ float sm[];
    const int tid = threadIdx.x;
    const long base = (long)blockIdx.x * 6912;

    float* fs   = sm;                 // [216][33]
    float* ovl  = sm + 7128;
    float* qn   = ovl;                // [24][36]
    float* kn   = ovl + 864;
    float* vn   = ovl + 1728;
    float* smx  = ovl + 2592;         // [8][24 x 25]
    float* smx2 = ovl + 7392;
    float* wq   = sm + 19320;         // [32][33]
    float* wk   = sm + 20376;
    float* wv   = sm + 21432;
    float* wm   = sm + 22488;
    float* bq   = sm + 23544;
    float* bk   = sm + 23576;
    float* bv   = sm + 23608;
    float* bm   = sm + 23640;
    float* aA   = sm + 23672;         // [32][33]
    float* sWL  = sm + 24728;         // 64
    float* sWC  = sm + 24792;         // 64
    float* bmx  = sm + 24856;         // 376
    float* sdl  = sm + 25296;         // 32 (sigmoid(gate)*delta)
    float* vc1  = sm + 25328;         // 32
    float* vc2  = sm + 25360;         // 32
    float* vc3  = sm + 25392;         // 32
    float* p1   = sm + 25424;         // [32][25]
    float* pp   = sm + 26224;         // [32][24]
    float* pbf  = sm + 26992;         // 24
    float* cvb  = sm + 27016;         // 32
    // overlays
    float* psum = smx;                // [32][8]
    float* psq  = smx + 256;          // [32][8]
    float* cw   = ovl;                // [288][33]
    float* pwT  = ovl;                // [24][25]
    float* p2   = ovl + 600;          // [32][25]

    const int j32 = tid & 31;
    const int g8  = tid >> 5;

    // ---------------- Phase 1: loads ----------------
    for (int idx = tid; idx < 6912; idx += NTHR) {
        int c = idx / 216, tl = idx % 216;
        fs[tl * 33 + c] = x[base + idx];
    }
    for (int idx = tid; idx < 1024; idx += NTHR) {
        int j = idx >> 5, i = idx & 31;      // global index = j*32 + i (row j)
        wq[i * 33 + j] = q_w[idx];
        wk[i * 33 + j] = k_w[idx];
        wv[i * 33 + j] = v_w[idx];
        wm[i * 33 + j] = m_w[idx];
        aA[j * 33 + i] = gA32[idx];
    }
    for (int idx = tid; idx < 768; idx += NTHR) pp[idx] = pre_prompt[idx];
    for (int idx = tid; idx < 376; idx += NTHR) bmx[idx] = gBmixr[idx];
    if (tid < 64) { sWL[tid] = W_logit[tid]; sWC[tid] = W_ctx[tid]; }
    if (tid < 32) {
        bq[tid] = q_b[tid]; bk[tid] = k_b[tid];
        bv[tid] = v_b[tid]; bm[tid] = m_b[tid];
        cvb[tid] = conv_b[tid];
    }
    if (tid < 24) pbf[tid] = p_b[tid];
    __syncthreads();

    // ---------------- Phase 2: per-channel stats ----------------
    {
        int c = tid >> 3, part = tid & 7;
        float s = 0.f, sq = 0.f;
        int tl0 = part * 27;
#pragma unroll 9
        for (int k2 = 0; k2 < 27; ++k2) {
            float v = fs[(tl0 + k2) * 33 + c];
            s += v; sq += v * v;
        }
        psum[c * 8 + part] = s;
        psq [c * 8 + part] = sq;
    }
    __syncthreads();

    // ---------------- Phase 2b: warp-0 scalar chain ----------------
    if (tid < 32) {
        const int c = tid;
        float s = 0.f, sq = 0.f;
#pragma unroll
        for (int p = 0; p < 8; ++p) { s += psum[c * 8 + p]; sq += psq[c * 8 + p]; }
        float pooled = s * (1.f / 216.f);
        float varu = (sq - s * s * (1.f / 216.f)) * (1.f / 215.f);
        float scalec = fmaxf(sqrtf(fmaxf(varu, 0.f)), 1e-3f);

        // LayerNorm across channels (biased var)
        float mu = pooled;
#pragma unroll
        for (int o = 16; o > 0; o >>= 1) mu += __shfl_xor_sync(0xffffffffu, mu, o);
        mu *= (1.f / 32.f);
        float d = pooled - mu;
        float var = d * d;
#pragma unroll
        for (int o = 16; o > 0; o >>= 1) var += __shfl_xor_sync(0xffffffffu, var, o);
        var *= (1.f / 32.f);
        float pn = d * rsqrtf(var + 1e-5f) * ln_g[c] + ln_b[c];
        vc1[c] = pn; __syncwarp();

        float acc = rp_b1[c];
#pragma unroll
        for (int i = 0; i < 32; ++i) acc += vc1[i] * rp_w1[c * 32 + i];
        vc2[c] = geluf(acc); __syncwarp();

        acc = rp_b2[c];
#pragma unroll
        for (int i = 0; i < 32; ++i) acc += vc2[i] * rp_w2[c * 32 + i];
        vc1[c] = acc; __syncwarp();       // pooled_rule

        acc = mask_b[c];
#pragma unroll
        for (int i = 0; i < 32; ++i) acc += vc1[i] * mask_w[c * 32 + i];
        float M = sigmoidf_(acc);

        acc = val_b1[c];
#pragma unroll
        for (int i = 0; i < 32; ++i) acc += vc1[i] * val_w1[c * 32 + i];
        vc2[c] = geluf(acc); __syncwarp();

        acc = val_b2[c];
#pragma unroll
        for (int i = 0; i < 32; ++i) acc += vc2[i] * val_w2[c * 32 + i];
        float v32 = tanhf(acc) * scalec + pooled;
        float xdo = (1.f - M) * pooled + M * v32;

        float y = xdo;
#pragma unroll
        for (int it = 0; it < 3; ++it) {
            vc3[c] = y; __syncwarp();
            float a2 = xdo;
#pragma unroll
            for (int j = 0; j < 32; ++j) a2 += vc3[j] * aA[c * 33 + j];
            y = a2;
            __syncwarp();
        }
        sdl[c] = sigmoidf_(fuse_gate[0]) * (y - pooled);
    }
    __syncthreads();

    // ---------------- Phase 3: fuse ----------------
    for (int idx = tid; idx < 6912; idx += NTHR) {
        int tl = idx >> 5, c = idx & 31;
        fs[tl * 33 + c] += sdl[c];
    }
    __syncthreads();

    // ---------------- Phase 4: attention per context t ----------------
    for (int t = 0; t < 9; ++t) {
        const int rowbase = t * 24;

        // 4a: q/k/v projections (raw)
        {
            float aq[3], ak[3], av[3];
#pragma unroll
            for (int r = 0; r < 3; ++r) { aq[r] = bq[j32]; ak[r] = bk[j32]; av[r] = bv[j32]; }
#pragma unroll 8
            for (int i = 0; i < 32; ++i) {
                float wqi = wq[i * 33 + j32];
                float wki = wk[i * 33 + j32];
                float wvi = wv[i * 33 + j32];
#pragma unroll
                for (int r = 0; r < 3; ++r) {
                    float f = fs[(rowbase + g8 * 3 + r) * 33 + i];
                    aq[r] = fmaf(f, wqi, aq[r]);
                    ak[r] = fmaf(f, wki, ak[r]);
                    av[r] = fmaf(f, wvi, av[r]);
                }
            }
#pragma unroll
            for (int r = 0; r < 3; ++r) {
                int l = g8 * 3 + r;
                qn[l * 36 + j32] = aq[r];
                kn[l * 36 + j32] = ak[r];
                vn[l * 36 + j32] = av[r];
            }
        }
        __syncthreads();

        // 4b: cosine normalization (0.5/sqrt(HD) folded into q)
        if (tid < 192) {
            int l = tid >> 3, h = tid & 7;
            float4* qp = (float4*)&qn[l * 36 + h * 4];
            float4 qv = *qp;
            float n2 = qv.x*qv.x + qv.y*qv.y + qv.z*qv.z + qv.w*qv.w;
            float inv = 0.5f / fmaxf(sqrtf(n2), 1e-12f);
            qv.x *= inv; qv.y *= inv; qv.z *= inv; qv.w *= inv;
            *qp = qv;
            float4* kp = (float4*)&kn[l * 36 + h * 4];
            float4 kv = *kp;
            n2 = kv.x*kv.x + kv.y*kv.y + kv.z*kv.z + kv.w*kv.w;
            inv = 1.f / fmaxf(sqrtf(n2), 1e-12f);
            kv.x *= inv; kv.y *= inv; kv.z *= inv; kv.w *= inv;
            *kp = kv;
            float4* vp = (float4*)&vn[l * 36 + h * 4];
            float4 vv = *vp;
            n2 = vv.x*vv.x + vv.y*vv.y + vv.z*vv.z + vv.w*vv.w;
            inv = 1.f / fmaxf(sqrtf(n2), 1e-12f);
            vv.x *= inv; vv.y *= inv; vv.z *= inv; vv.w *= inv;
            *vp = vv;
        }
        __syncthreads();

        // 4c: logits + W_logit mix + rel-pos bias (raw logits stay in regs)
        for (int p = tid; p < 576; p += NTHR) {
            int i = p / 24, j = p % 24;
            float raw[8];
#pragma unroll
            for (int h = 0; h < 8; ++h) {
                float4 qv = *(float4*)&qn[i * 36 + h * 4];
                float4 kv = *(float4*)&kn[j * 36 + h * 4];
                raw[h] = qv.x*kv.x + qv.y*kv.y + qv.z*kv.z + qv.w*kv.w;
            }
            int rel = i - j + 23;   // always in [0,46]
#pragma unroll
            for (int Ho = 0; Ho < 8; ++Ho) {
                float acc = bmx[Ho * 47 + rel];
#pragma unroll
                for (int h = 0; h < 8; ++h) acc = fmaf(raw[h], sWL[h * 8 + Ho], acc);
                smx[Ho * 600 + i * 25 + j] = acc;
            }
        }
        __syncthreads();

        // 4d: softmax over j (one thread per (Ho,i) row)
        if (tid < 192) {
            int Ho = tid / 24, i = tid % 24;
            float* row = &smx[Ho * 600 + i * 25];
            float mx = row[0];
#pragma unroll
            for (int j = 1; j < 24; ++j) mx = fmaxf(mx, row[j]);
            float e[24];
            float ssum = 0.f;
#pragma unroll
            for (int j = 0; j < 24; ++j) { e[j] = __expf(row[j] - mx); ssum += e[j]; }
            float inv = 1.f / ssum;
#pragma unroll
            for (int j = 0; j < 24; ++j) row[j] = e[j] * inv;
        }
        __syncthreads();

        // 4e: W_ctx mix
        for (int p = tid; p < 576; p += NTHR) {
            int i = p / 24, j = p % 24;
            float sv[8];
#pragma unroll
            for (int h = 0; h < 8; ++h) sv[h] = smx[h * 600 + i * 25 + j];
#pragma unroll
            for (int Ho = 0; Ho < 8; ++Ho) {
                float acc = 0.f;
#pragma unroll
                for (int h = 0; h < 8; ++h) acc = fmaf(sv[h], sWC[h * 8 + Ho], acc);
                smx2[Ho * 600 + i * 25 + j] = acc;
            }
        }
        __syncthreads();

        // 4f: AV -> att (reuse qn buffer)
        {
            int h = j32 >> 2;
            float acc[3] = {0.f, 0.f, 0.f};
#pragma unroll 8
            for (int jj = 0; jj < 24; ++jj) {
                float vv = vn[jj * 36 + j32];
#pragma unroll
                for (int r = 0; r < 3; ++r)
                    acc[r] = fmaf(smx2[h * 600 + (g8 * 3 + r) * 25 + jj], vv, acc[r]);
            }
#pragma unroll
            for (int r = 0; r < 3; ++r) qn[(g8 * 3 + r) * 36 + j32] = acc[r];
        }
        __syncthreads();

        // 4g: output projection, write x_att in place over fs rows of this t
        {
            float am[3];
#pragma unroll
            for (int r = 0; r < 3; ++r) am[r] = bm[j32];
#pragma unroll 8
            for (int i = 0; i < 32; ++i) {
                float wmi = wm[i * 33 + j32];
#pragma unroll
                for (int r = 0; r < 3; ++r)
                    am[r] = fmaf(qn[(g8 * 3 + r) * 36 + i], wmi, am[r]);
            }
#pragma unroll
            for (int r = 0; r < 3; ++r)
                fs[(rowbase + g8 * 3 + r) * 33 + j32] = am[r];
        }
        __syncthreads();
    }

    // ---------------- Phase 5: conv over contexts ----------------
    // stage transposed conv weights over the freed attention buffers
    for (int idx = tid; idx < 9216; idx += NTHR) {
        int o = idx / 288, rem = idx % 288;   // rem = i*9 + kt
        cw[rem * 33 + o] = conv_w[idx];
    }
    __syncthreads();
    {
        float acc[3];
#pragma unroll
        for (int r = 0; r < 3; ++r) acc[r] = cvb[j32];
        for (int i = 0; i < 32; ++i) {
#pragma unroll
            for (int kt = 0; kt < 8; ++kt) {
                float w = cw[(i * 9 + kt) * 33 + j32];
#pragma unroll
                for (int r = 0; r < 3; ++r)
                    acc[r] = fmaf(fs[(kt * 24 + g8 * 3 + r) * 33 + i], w, acc[r]);
            }
            float w8 = cw[(i * 9 + 8) * 33 + j32];
#pragma unroll
            for (int r = 0; r < 3; ++r)
                acc[r] = fmaf(pp[i * 24 + g8 * 3 + r], w8, acc[r]);
        }
#pragma unroll
        for (int r = 0; r < 3; ++r)
            p1[j32 * 25 + g8 * 3 + r] = fmaxf(acc[r], 0.f);
    }
    __syncthreads();

    // ---------------- Phase 6: token linear ----------------
    for (int idx = tid; idx < 576; idx += NTHR) {
        int lo = idx / 24, l = idx % 24;
        pwT[l * 25 + lo] = p_w[idx];
    }
    __syncthreads();
    for (int idx = tid; idx < 768; idx += NTHR) {
        int o = idx / 24, lo = idx % 24;
        float acc = pbf[lo];
#pragma unroll
        for (int l = 0; l < 24; ++l)
            acc = fmaf(p1[o * 25 + l], pwT[l * 25 + lo], acc);
        p2[o * 25 + lo] = acc;
    }
    __syncthreads();

    // ---------------- Phase 7: output ----------------
    for (int idx = tid; idx < 6912; idx += NTHR) {
        int c = idx / 216, tl = idx % 216;
        float v = fs[tl * 33 + c];
        if (tl >= 192) v -= p2[c * 25 + (tl - 192)];
        out[base + idx] = v;
    }
}

extern "C" void kernel_launch(void* const* d_in, const int* in_sizes, int n_in,
                              void* d_out, int out_size) {
    const float* x        = (const float*)d_in[0];
    const float* ln_g     = (const float*)d_in[1];
    const float* ln_b     = (const float*)d_in[2];
    const float* rp_w1    = (const float*)d_in[3];
    const float* rp_b1    = (const float*)d_in[4];
    const float* rp_w2    = (const float*)d_in[5];
    const float* rp_b2    = (const float*)d_in[6];
    const float* W_causal = (const float*)d_in[7];
    const float* mask_w   = (const float*)d_in[8];
    const float* mask_b   = (const float*)d_in[9];
    const float* val_w1   = (const float*)d_in[10];
    const float* val_b1   = (const float*)d_in[11];
    const float* val_w2   = (const float*)d_in[12];
    const float* val_b2   = (const float*)d_in[13];
    const float* fuse_g   = (const float*)d_in[14];
    const float* q_w      = (const float*)d_in[15];
    const float* q_b      = (const float*)d_in[16];
    const float* k_w      = (const float*)d_in[17];
    const float* k_b      = (const float*)d_in[18];
    const float* v_w      = (const float*)d_in[19];
    const float* v_b      = (const float*)d_in[20];
    const float* m_w      = (const float*)d_in[21];
    const float* m_b      = (const float*)d_in[22];
    const float* W_logit  = (const float*)d_in[23];
    const float* W_ctx    = (const float*)d_in[24];
    const float* rpb      = (const float*)d_in[25];
    const float* pre_p    = (const float*)d_in[26];
    const float* conv_w   = (const float*)d_in[27];
    const float* conv_b   = (const float*)d_in[28];
    const float* p_w      = (const float*)d_in[29];
    const float* p_b      = (const float*)d_in[30];
    float* out = (float*)d_out;

    const int smem_bytes = 27048 * 4;
    cudaFuncSetAttribute(prb_kernel, cudaFuncAttributeMaxDynamicSharedMemorySize,
                         smem_bytes);

    prb_precompute<<<1, 128>>>(W_causal, W_logit, rpb);

    int B = in_sizes[0] / 6912;
    prb_kernel<<<B, NTHR, smem_bytes>>>(
        x, ln_g, ln_b, rp_w1, rp_b1, rp_w2, rp_b2,
        mask_w, mask_b, val_w1, val_b1, val_w2, val_b2, fuse_g,
        q_w, q_b, k_w, k_b, v_w, v_b, m_w, m_b,
        W_logit, W_ctx, pre_p, conv_w, conv_b, p_w, p_b, out);
}

// round 6
// speedup vs baseline: 1.3344x; 1.3344x over previous
#include <cuda_runtime.h>
#include <cuda_bf16.h>
#include <math.h>

// ============================================================================
// PredictiveReasoningBlock fused kernel. One CTA per batch element.
// Shapes: B=4096, D=32, T=9, L=24, H=8, HD=4.
// Round 5: R4 wavefront-count optimizations, compile fix (conv_w as param).
// ============================================================================

#define NTHR 256

// batch-invariant precomputed terms
__device__ float gA32[1024];    // 0.9*softplus(W_causal)*(1-I), row-normalized
__device__ float gBmixr[376];   // sum_h W_logit[h,Ho]*rel_pos_bias[h,r]  (8 x 47)
__device__ float gPPC[768];     // conv_b[o] + sum_i conv_w[o,i,8]*pre_prompt[i,l]

__device__ __forceinline__ float geluf(float x) {
    return 0.5f * x * (1.0f + erff(x * 0.7071067811865476f));
}
__device__ __forceinline__ float sigmoidf_(float x) {
    return 1.0f / (1.0f + __expf(-x));
}

__global__ void prb_precompute(const float* __restrict__ Wc,
                               const float* __restrict__ WL,
                               const float* __restrict__ rpb,
                               const float* __restrict__ conv_w,
                               const float* __restrict__ conv_b,
                               const float* __restrict__ pre_prompt) {
    int tid = threadIdx.x;
    if (tid < 32) {
        float a[32];
        float rs = 0.f;
#pragma unroll
        for (int j = 0; j < 32; ++j) {
            float w = Wc[tid * 32 + j];
            float sp = (w > 20.f) ? w : log1pf(expf(w));
            if (j == tid) sp = 0.f;
            a[j] = sp;
            rs += sp;
        }
        float inv = 0.9f / (rs + 1e-6f);
#pragma unroll
        for (int j = 0; j < 32; ++j) gA32[tid * 32 + j] = a[j] * inv;
    }
    for (int idx = tid; idx < 376; idx += blockDim.x) {
        int Ho = idx / 47, r = idx % 47;
        float s = 0.f;
#pragma unroll
        for (int h = 0; h < 8; ++h) s += WL[h * 8 + Ho] * rpb[h * 47 + r];
        gBmixr[idx] = s;
    }
    for (int idx = tid; idx < 768; idx += blockDim.x) {
        int o = idx / 24, l = idx % 24;
        float s = conv_b[o];
#pragma unroll
        for (int i = 0; i < 32; ++i)
            s += conv_w[(o * 32 + i) * 9 + 8] * pre_prompt[i * 24 + l];
        gPPC[idx] = s;
    }
}

// ---------------------------------------------------------------------------
// shared memory layout (floats)
// ---------------------------------------------------------------------------
#define S_FS    0        // fused/x_att tile [216][33]
#define S_OVL   7128     // overlay region
//   attention: q3/k3/v3 [72][36] each (7776) + smx [8][625] (5000)
//   conv:      cw [288][33] (9504)
//   phase6:    pwT [24][25] + p2 [32][25]
//   stats:     psum/psq [32][8] each
#define S_Q3    (S_OVL)
#define S_K3    (S_OVL + 2592)
#define S_V3    (S_OVL + 5184)
#define S_SMX   (S_OVL + 7776)
#define S_WQ    19904    // [32][33] transposed weights
#define S_WK    20960
#define S_WV    22016
#define S_WM    23072
#define S_BQ    24128
#define S_BK    24160
#define S_BV    24192
#define S_BM    24224
#define S_AA    24256    // [32][33]
#define S_SWL   25312    // 64
#define S_SWC   25376    // 64
#define S_BMX   25440    // 376
#define S_SDL   25816    // 32
#define S_VC1   25848
#define S_VC2   25880
#define S_VC3   25912
#define S_P1    25944    // [32][25]
#define S_PPC   26744    // [32][25]
#define S_PBF   27544    // 24
#define S_TOTAL 27568

__global__ __launch_bounds__(NTHR, 2)
void prb_kernel(const float* __restrict__ x,
                const float* __restrict__ ln_g,  const float* __restrict__ ln_b,
                const float* __restrict__ rp_w1, const float* __restrict__ rp_b1,
                const float* __restrict__ rp_w2, const float* __restrict__ rp_b2,
                const float* __restrict__ mask_w, const float* __restrict__ mask_b,
                const float* __restrict__ val_w1, const float* __restrict__ val_b1,
                const float* __restrict__ val_w2, const float* __restrict__ val_b2,
                const float* __restrict__ fuse_gate,
                const float* __restrict__ q_w, const float* __restrict__ q_b,
                const float* __restrict__ k_w, const float* __restrict__ k_b,
                const float* __restrict__ v_w, const float* __restrict__ v_b,
                const float* __restrict__ m_w, const float* __restrict__ m_b,
                const float* __restrict__ W_logit, const float* __restrict__ W_ctx,
                const float* __restrict__ conv_w,
                const float* __restrict__ p_w,   const float* __restrict__ p_b,
                float* __restrict__ out)
{
    extern __shared__ float sm[];
    const int tid = threadIdx.x;
    const long base = (long)blockIdx.x * 6912;

    float* fs  = sm + S_FS;
    float* q3  = sm + S_Q3;
    float* k3  = sm + S_K3;
    float* v3  = sm + S_V3;
    float* smx = sm + S_SMX;
    float* wq  = sm + S_WQ;
    float* wk  = sm + S_WK;
    float* wv  = sm + S_WV;
    float* wm  = sm + S_WM;
    float* bq  = sm + S_BQ;
    float* bk  = sm + S_BK;
    float* bv  = sm + S_BV;
    float* bm  = sm + S_BM;
    float* aA  = sm + S_AA;
    float* sWL = sm + S_SWL;
    float* sWC = sm + S_SWC;
    float* bmx = sm + S_BMX;
    float* sdl = sm + S_SDL;
    float* vc1 = sm + S_VC1;
    float* vc2 = sm + S_VC2;
    float* vc3 = sm + S_VC3;
    float* p1  = sm + S_P1;
    float* ppc = sm + S_PPC;
    float* pbf = sm + S_PBF;
    // overlays
    float* psum = sm + S_OVL;          // [32][8]
    float* psq  = sm + S_OVL + 256;
    float* cw   = sm + S_OVL;          // [288][33]
    float* pwT  = sm + S_OVL;          // [24][25]
    float* p2   = sm + S_OVL + 600;    // [32][25]

    const int j32 = tid & 31;
    const int g8  = tid >> 5;

    // ---------------- Phase 1: loads ----------------
    for (int idx = tid; idx < 6912; idx += NTHR) {
        int c = idx / 216, tl = idx % 216;
        fs[tl * 33 + c] = x[base + idx];
    }
    for (int idx = tid; idx < 1024; idx += NTHR) {
        int j = idx >> 5, i = idx & 31;
        wq[i * 33 + j] = q_w[idx];
        wk[i * 33 + j] = k_w[idx];
        wv[i * 33 + j] = v_w[idx];
        wm[i * 33 + j] = m_w[idx];
        aA[j * 33 + i] = gA32[idx];
    }
    for (int idx = tid; idx < 768; idx += NTHR) {
        int o = idx / 24, l = idx % 24;
        ppc[o * 25 + l] = gPPC[idx];
    }
    for (int idx = tid; idx < 376; idx += NTHR) bmx[idx] = gBmixr[idx];
    if (tid < 64) { sWL[tid] = W_logit[tid]; sWC[tid] = W_ctx[tid]; }
    if (tid < 32) {
        bq[tid] = q_b[tid]; bk[tid] = k_b[tid];
        bv[tid] = v_b[tid]; bm[tid] = m_b[tid];
    }
    if (tid < 24) pbf[tid] = p_b[tid];
    __syncthreads();

    // ---------------- Phase 2: per-channel stats (on raw x) ----------------
    {
        int c = tid >> 3, part = tid & 7;
        float s = 0.f, sq = 0.f;
        int tl0 = part * 27;
#pragma unroll 9
        for (int k2 = 0; k2 < 27; ++k2) {
            float v = fs[(tl0 + k2) * 33 + c];
            s += v; sq += v * v;
        }
        psum[c * 8 + part] = s;
        psq [c * 8 + part] = sq;
    }
    __syncthreads();

    // ---------------- Phase 2b: warp-0 scalar chain ----------------
    if (tid < 32) {
        const int c = tid;
        float s = 0.f, sq = 0.f;
#pragma unroll
        for (int p = 0; p < 8; ++p) { s += psum[c * 8 + p]; sq += psq[c * 8 + p]; }
        float pooled = s * (1.f / 216.f);
        float varu = (sq - s * s * (1.f / 216.f)) * (1.f / 215.f);
        float scalec = fmaxf(sqrtf(fmaxf(varu, 0.f)), 1e-3f);

        float mu = pooled;
#pragma unroll
        for (int o = 16; o > 0; o >>= 1) mu += __shfl_xor_sync(0xffffffffu, mu, o);
        mu *= (1.f / 32.f);
        float d = pooled - mu;
        float var = d * d;
#pragma unroll
        for (int o = 16; o > 0; o >>= 1) var += __shfl_xor_sync(0xffffffffu, var, o);
        var *= (1.f / 32.f);
        float pn = d * rsqrtf(var + 1e-5f) * ln_g[c] + ln_b[c];
        vc1[c] = pn; __syncwarp();

        float acc = rp_b1[c];
#pragma unroll
        for (int i = 0; i < 32; ++i) acc += vc1[i] * rp_w1[c * 32 + i];
        vc2[c] = geluf(acc); __syncwarp();

        acc = rp_b2[c];
#pragma unroll
        for (int i = 0; i < 32; ++i) acc += vc2[i] * rp_w2[c * 32 + i];
        vc1[c] = acc; __syncwarp();       // pooled_rule

        acc = mask_b[c];
#pragma unroll
        for (int i = 0; i < 32; ++i) acc += vc1[i] * mask_w[c * 32 + i];
        float M = sigmoidf_(acc);

        acc = val_b1[c];
#pragma unroll
        for (int i = 0; i < 32; ++i) acc += vc1[i] * val_w1[c * 32 + i];
        vc2[c] = geluf(acc); __syncwarp();

        acc = val_b2[c];
#pragma unroll
        for (int i = 0; i < 32; ++i) acc += vc2[i] * val_w2[c * 32 + i];
        float v32 = tanhf(acc) * scalec + pooled;
        float xdo = (1.f - M) * pooled + M * v32;

        float y = xdo;
#pragma unroll
        for (int it = 0; it < 3; ++it) {
            vc3[c] = y; __syncwarp();
            float a2 = xdo;
#pragma unroll
            for (int j = 0; j < 32; ++j) a2 += vc3[j] * aA[c * 33 + j];
            y = a2;
            __syncwarp();
        }
        sdl[c] = sigmoidf_(fuse_gate[0]) * (y - pooled);
    }
    __syncthreads();

    // ---------------- Phase 4: attention, chunks of 3 contexts ----------------
    for (int tc = 0; tc < 3; ++tc) {
        const int rowbase = tc * 72;
        const int crow = g8 * 9;     // this thread's base row within chunk

        // 4a: q/k/v projections for 72 rows (fuse folded in via sdl)
        {
            float aq[9], ak[9], av[9];
#pragma unroll
            for (int r = 0; r < 9; ++r) { aq[r] = bq[j32]; ak[r] = bk[j32]; av[r] = bv[j32]; }
#pragma unroll 4
            for (int i = 0; i < 32; ++i) {
                float wqi = wq[i * 33 + j32];
                float wki = wk[i * 33 + j32];
                float wvi = wv[i * 33 + j32];
                float sd  = sdl[i];
#pragma unroll
                for (int r = 0; r < 9; ++r) {
                    float f = fs[(rowbase + crow + r) * 33 + i] + sd;
                    aq[r] = fmaf(f, wqi, aq[r]);
                    ak[r] = fmaf(f, wki, ak[r]);
                    av[r] = fmaf(f, wvi, av[r]);
                }
            }
#pragma unroll
            for (int r = 0; r < 9; ++r) {
                q3[(crow + r) * 36 + j32] = aq[r];
                k3[(crow + r) * 36 + j32] = ak[r];
                v3[(crow + r) * 36 + j32] = av[r];
            }
        }
        __syncthreads();

        // 4b: cosine normalization for the chunk (0.5/sqrt(HD) folded into q)
        for (int p = tid; p < 576; p += NTHR) {
            int l = p >> 3, h = p & 7;
            float4* qp = (float4*)&q3[l * 36 + h * 4];
            float4 qv = *qp;
            float n2 = qv.x*qv.x + qv.y*qv.y + qv.z*qv.z + qv.w*qv.w;
            float inv = 0.5f / fmaxf(sqrtf(n2), 1e-12f);
            qv.x *= inv; qv.y *= inv; qv.z *= inv; qv.w *= inv;
            *qp = qv;
            float4* kp = (float4*)&k3[l * 36 + h * 4];
            float4 kv = *kp;
            n2 = kv.x*kv.x + kv.y*kv.y + kv.z*kv.z + kv.w*kv.w;
            inv = 1.f / fmaxf(sqrtf(n2), 1e-12f);
            kv.x *= inv; kv.y *= inv; kv.z *= inv; kv.w *= inv;
            *kp = kv;
            float4* vp = (float4*)&v3[l * 36 + h * 4];
            float4 vv = *vp;
            n2 = vv.x*vv.x + vv.y*vv.y + vv.z*vv.z + vv.w*vv.w;
            inv = 1.f / fmaxf(sqrtf(n2), 1e-12f);
            vv.x *= inv; vv.y *= inv; vv.z *= inv; vv.w *= inv;
            *vp = vv;
        }
        __syncthreads();

        for (int t3 = 0; t3 < 3; ++t3) {
            const int ro = t3 * 24;

            // 4c: logits + W_logit mix (bias deferred to softmax).
            // Warp covers 4 i x 8 jg -> q/k LDS.128 dedup within warp.
            if (tid < 192) {
                const int i = tid >> 3, jg = tid & 7;
                float raw[3][8];
#pragma unroll
                for (int h = 0; h < 8; ++h) {
                    float4 qh = *(const float4*)&q3[(ro + i) * 36 + h * 4];
#pragma unroll
                    for (int r = 0; r < 3; ++r) {
                        float4 kv = *(const float4*)&k3[(ro + jg * 3 + r) * 36 + h * 4];
                        raw[r][h] = qh.x*kv.x + qh.y*kv.y + qh.z*kv.z + qh.w*kv.w;
                    }
                }
#pragma unroll
                for (int Ho = 0; Ho < 8; ++Ho) {
                    float wl[8];
#pragma unroll
                    for (int h = 0; h < 8; ++h) wl[h] = sWL[h * 8 + Ho];
#pragma unroll
                    for (int r = 0; r < 3; ++r) {
                        float acc = 0.f;
#pragma unroll
                        for (int h = 0; h < 8; ++h) acc = fmaf(raw[r][h], wl[h], acc);
                        smx[Ho * 625 + i * 25 + jg * 3 + r] = acc;
                    }
                }
            }
            __syncthreads();

            // 4d: softmax (adds rel-pos bias here: bmx[Ho][i-j+23])
            if (tid < 192) {
                const int Ho = tid / 24, i = tid % 24;
                float* row = &smx[Ho * 625 + i * 25];
                const float* brow = &bmx[Ho * 47 + i + 23];
                float e[24];
                float mx = -1e30f;
#pragma unroll
                for (int j = 0; j < 24; ++j) {
                    e[j] = row[j] + brow[-j];
                    mx = fmaxf(mx, e[j]);
                }
                float ssum = 0.f;
#pragma unroll
                for (int j = 0; j < 24; ++j) { e[j] = __expf(e[j] - mx); ssum += e[j]; }
                float inv = 1.f / ssum;
#pragma unroll
                for (int j = 0; j < 24; ++j) row[j] = e[j] * inv;
            }
            __syncthreads();

            // 4e: W_ctx mix, in place (each (i,j) column owned by one thread)
            if (tid < 192) {
                const int i = tid >> 3, jg = tid & 7;
                float sv[3][8];
#pragma unroll
                for (int h = 0; h < 8; ++h)
#pragma unroll
                    for (int r = 0; r < 3; ++r)
                        sv[r][h] = smx[h * 625 + i * 25 + jg * 3 + r];
#pragma unroll
                for (int Ho = 0; Ho < 8; ++Ho) {
                    float wc[8];
#pragma unroll
                    for (int h = 0; h < 8; ++h) wc[h] = sWC[h * 8 + Ho];
#pragma unroll
                    for (int r = 0; r < 3; ++r) {
                        float acc = 0.f;
#pragma unroll
                        for (int h = 0; h < 8; ++h) acc = fmaf(sv[r][h], wc[h], acc);
                        smx[Ho * 625 + i * 25 + jg * 3 + r] = acc;
                    }
                }
            }
            __syncthreads();

            // 4f: AV -> write att back into q3 rows of this t3
            {
                const int h = j32 >> 2;
                float acc[3] = {0.f, 0.f, 0.f};
#pragma unroll 8
                for (int jj = 0; jj < 24; ++jj) {
                    float vv = v3[(ro + jj) * 36 + j32];
#pragma unroll
                    for (int r = 0; r < 3; ++r)
                        acc[r] = fmaf(smx[h * 625 + (g8 * 3 + r) * 25 + jj], vv, acc[r]);
                }
#pragma unroll
                for (int r = 0; r < 3; ++r)
                    q3[(ro + g8 * 3 + r) * 36 + j32] = acc[r];
            }
            __syncthreads();
        }

        // 4g: output projection for the whole chunk, overwrite fs rows
        {
            float am[9];
#pragma unroll
            for (int r = 0; r < 9; ++r) am[r] = bm[j32];
#pragma unroll 4
            for (int i = 0; i < 32; ++i) {
                float wmi = wm[i * 33 + j32];
#pragma unroll
                for (int r = 0; r < 9; ++r)
                    am[r] = fmaf(q3[(crow + r) * 36 + i], wmi, am[r]);
            }
#pragma unroll
            for (int r = 0; r < 9; ++r)
                fs[(rowbase + crow + r) * 33 + j32] = am[r];
        }
        __syncthreads();
    }

    // ---------------- Phase 5: conv over contexts ----------------
    for (int idx = tid; idx < 9216; idx += NTHR) {
        int o = idx / 288, rem = idx % 288;   // rem = i*9 + kt
        cw[rem * 33 + o] = conv_w[idx];
    }
    __syncthreads();
    if (g8 < 4) {
        const int lbase = g8 * 6;
        float acc[6];
#pragma unroll
        for (int r = 0; r < 6; ++r) acc[r] = ppc[j32 * 25 + lbase + r];
#pragma unroll 2
        for (int i = 0; i < 32; ++i) {
#pragma unroll
            for (int kt = 0; kt < 8; ++kt) {
                float w = cw[(i * 9 + kt) * 33 + j32];
#pragma unroll
                for (int r = 0; r < 6; ++r)
                    acc[r] = fmaf(fs[(kt * 24 + lbase + r) * 33 + i], w, acc[r]);
            }
        }
#pragma unroll
        for (int r = 0; r < 6; ++r)
            p1[j32 * 25 + lbase + r] = fmaxf(acc[r], 0.f);
    }
    __syncthreads();

    // ---------------- Phase 6: token linear ----------------
    for (int idx = tid; idx < 576; idx += NTHR) {
        int lo = idx / 24, l = idx % 24;
        pwT[l * 25 + lo] = p_w[idx];
    }
    __syncthreads();
    for (int idx = tid; idx < 768; idx += NTHR) {
        int o = idx / 24, lo = idx % 24;
        float acc = pbf[lo];
#pragma unroll
        for (int l = 0; l < 24; ++l)
            acc = fmaf(p1[o * 25 + l], pwT[l * 25 + lo], acc);
        p2[o * 25 + lo] = acc;
    }
    __syncthreads();

    // ---------------- Phase 7: output ----------------
    for (int idx = tid; idx < 6912; idx += NTHR) {
        int c = idx / 216, tl = idx % 216;
        float v = fs[tl * 33 + c];
        if (tl >= 192) v -= p2[c * 25 + (tl - 192)];
        out[base + idx] = v;
    }
}

extern "C" void kernel_launch(void* const* d_in, const int* in_sizes, int n_in,
                              void* d_out, int out_size) {
    const float* x        = (const float*)d_in[0];
    const float* ln_g     = (const float*)d_in[1];
    const float* ln_b     = (const float*)d_in[2];
    const float* rp_w1    = (const float*)d_in[3];
    const float* rp_b1    = (const float*)d_in[4];
    const float* rp_w2    = (const float*)d_in[5];
    const float* rp_b2    = (const float*)d_in[6];
    const float* W_causal = (const float*)d_in[7];
    const float* mask_w   = (const float*)d_in[8];
    const float* mask_b   = (const float*)d_in[9];
    const float* val_w1   = (const float*)d_in[10];
    const float* val_b1   = (const float*)d_in[11];
    const float* val_w2   = (const float*)d_in[12];
    const float* val_b2   = (const float*)d_in[13];
    const float* fuse_g   = (const float*)d_in[14];
    const float* q_w      = (const float*)d_in[15];
    const float* q_b      = (const float*)d_in[16];
    const float* k_w      = (const float*)d_in[17];
    const float* k_b      = (const float*)d_in[18];
    const float* v_w      = (const float*)d_in[19];
    const float* v_b      = (const float*)d_in[20];
    const float* m_w      = (const float*)d_in[21];
    const float* m_b      = (const float*)d_in[22];
    const float* W_logit  = (const float*)d_in[23];
    const float* W_ctx    = (const float*)d_in[24];
    const float* rpb      = (const float*)d_in[25];
    const float* pre_p    = (const float*)d_in[26];
    const float* conv_w   = (const float*)d_in[27];
    const float* conv_b   = (const float*)d_in[28];
    const float* p_w      = (const float*)d_in[29];
    const float* p_b      = (const float*)d_in[30];
    float* out = (float*)d_out;

    const int smem_bytes = S_TOTAL * 4;
    cudaFuncSetAttribute(prb_kernel, cudaFuncAttributeMaxDynamicSharedMemorySize,
                         smem_bytes);

    prb_precompute<<<1, 256>>>(W_causal, W_logit, rpb, conv_w, conv_b, pre_p);

    int B = in_sizes[0] / 6912;
    prb_kernel<<<B, NTHR, smem_bytes>>>(
        x, ln_g, ln_b, rp_w1, rp_b1, rp_w2, rp_b2,
        mask_w, mask_b, val_w1, val_b1, val_w2, val_b2, fuse_g,
        q_w, q_b, k_w, k_b, v_w, v_b, m_w, m_b,
        W_logit, W_ctx, conv_w, p_w, p_b, out);
}

// round 7
// speedup vs baseline: 1.3749x; 1.0303x over previous
#include <cuda_runtime.h>
#include <cuda_bf16.h>
#include <math.h>

// ============================================================================
// PredictiveReasoningBlock fused kernel. One CTA per batch element.
// Shapes: B=4096, D=32, T=9, L=24, H=8, HD=4.
// Round 6: wavefront reduction — float4 broadcasts (fs stride 36), norm folded
// into qkv epilogue via shfl (4b deleted), smx layout [Ho*676+i*28+j] for
// vectorized softmax/AV, conv float4 broadcasts.
// ============================================================================

#define NTHR 256

// batch-invariant precomputed terms
__device__ float gA32[1024];    // 0.9*softplus(W_causal)*(1-I), row-normalized
__device__ float gBmixr[376];   // sum_h W_logit[h,Ho]*rel_pos_bias[h,r]  (8 x 47)
__device__ float gPPC[768];     // conv_b[o] + sum_i conv_w[o,i,8]*pre_prompt[i,l]

__device__ __forceinline__ float geluf(float x) {
    return 0.5f * x * (1.0f + erff(x * 0.7071067811865476f));
}
__device__ __forceinline__ float sigmoidf_(float x) {
    return 1.0f / (1.0f + __expf(-x));
}

__global__ void prb_precompute(const float* __restrict__ Wc,
                               const float* __restrict__ WL,
                               const float* __restrict__ rpb,
                               const float* __restrict__ conv_w,
                               const float* __restrict__ conv_b,
                               const float* __restrict__ pre_prompt) {
    int tid = threadIdx.x;
    if (tid < 32) {
        float a[32];
        float rs = 0.f;
#pragma unroll
        for (int j = 0; j < 32; ++j) {
            float w = Wc[tid * 32 + j];
            float sp = (w > 20.f) ? w : log1pf(expf(w));
            if (j == tid) sp = 0.f;
            a[j] = sp;
            rs += sp;
        }
        float inv = 0.9f / (rs + 1e-6f);
#pragma unroll
        for (int j = 0; j < 32; ++j) gA32[tid * 32 + j] = a[j] * inv;
    }
    for (int idx = tid; idx < 376; idx += blockDim.x) {
        int Ho = idx / 47, r = idx % 47;
        float s = 0.f;
#pragma unroll
        for (int h = 0; h < 8; ++h) s += WL[h * 8 + Ho] * rpb[h * 47 + r];
        gBmixr[idx] = s;
    }
    for (int idx = tid; idx < 768; idx += blockDim.x) {
        int o = idx / 24, l = idx % 24;
        float s = conv_b[o];
#pragma unroll
        for (int i = 0; i < 32; ++i)
            s += conv_w[(o * 32 + i) * 9 + 8] * pre_prompt[i * 24 + l];
        gPPC[idx] = s;
    }
}

// ---------------------------------------------------------------------------
// shared memory layout (floats)
// ---------------------------------------------------------------------------
#define S_FS    0                 // [216][36] fused/x_att tile
#define S_OVL   7776              // overlay region (13184)
#define S_Q3    (S_OVL)           // [72][36]
#define S_K3    (S_OVL + 2592)
#define S_V3    (S_OVL + 5184)
#define S_SMX   (S_OVL + 7776)    // [8]*676: rows [24]*28
// stats overlay:
#define S_PSUM  (S_OVL)           // [32][8]
#define S_PSQ   (S_OVL + 256)
#define S_AA    (S_OVL + 512)     // [32][33]
// conv overlay:
#define S_CW    (S_OVL)           // [288][33]
#define S_PPC   (S_OVL + 9504)    // [32][25]
#define S_P1    (S_OVL + 10304)   // [32][25]
// phase6/7 overlay:
#define S_P2    (S_OVL)           // [32][25]
// fixed tail
#define S_WQ    20960             // [32][33]
#define S_WK    22016
#define S_WV    23072
#define S_WM    24128
#define S_BQ    25184
#define S_BK    25216
#define S_BV    25248
#define S_BM    25280
#define S_SWL   25312
#define S_SWC   25376
#define S_BMX   25440             // 376 (pad 384)
#define S_SDL   25824             // 32, 16B aligned
#define S_VC1   25856
#define S_VC2   25888
#define S_VC3   25920
#define S_PBF   25952
#define S_PWT   25984             // [24][25]
#define S_TOTAL 26592

__global__ __launch_bounds__(NTHR, 2)
void prb_kernel(const float* __restrict__ x,
                const float* __restrict__ ln_g,  const float* __restrict__ ln_b,
                const float* __restrict__ rp_w1, const float* __restrict__ rp_b1,
                const float* __restrict__ rp_w2, const float* __restrict__ rp_b2,
                const float* __restrict__ mask_w, const float* __restrict__ mask_b,
                const float* __restrict__ val_w1, const float* __restrict__ val_b1,
                const float* __restrict__ val_w2, const float* __restrict__ val_b2,
                const float* __restrict__ fuse_gate,
                const float* __restrict__ q_w, const float* __restrict__ q_b,
                const float* __restrict__ k_w, const float* __restrict__ k_b,
                const float* __restrict__ v_w, const float* __restrict__ v_b,
                const float* __restrict__ m_w, const float* __restrict__ m_b,
                const float* __restrict__ W_logit, const float* __restrict__ W_ctx,
                const float* __restrict__ conv_w,
                const float* __restrict__ p_w,   const float* __restrict__ p_b,
                float* __restrict__ out)
{
    extern __shared__ float sm[];
    const int tid = threadIdx.x;
    const long base = (long)blockIdx.x * 6912;

    float* fs  = sm + S_FS;
    float* q3  = sm + S_Q3;
    float* k3  = sm + S_K3;
    float* v3  = sm + S_V3;
    float* smx = sm + S_SMX;
    float* wq  = sm + S_WQ;
    float* wk  = sm + S_WK;
    float* wv  = sm + S_WV;
    float* wm  = sm + S_WM;
    float* bq  = sm + S_BQ;
    float* bk  = sm + S_BK;
    float* bv  = sm + S_BV;
    float* bm  = sm + S_BM;
    float* sWL = sm + S_SWL;
    float* sWC = sm + S_SWC;
    float* bmx = sm + S_BMX;
    float* sdl = sm + S_SDL;
    float* vc1 = sm + S_VC1;
    float* vc2 = sm + S_VC2;
    float* vc3 = sm + S_VC3;
    float* pbf = sm + S_PBF;
    float* pwT = sm + S_PWT;
    float* aA  = sm + S_AA;
    float* psum = sm + S_PSUM;
    float* psq  = sm + S_PSQ;
    float* cw   = sm + S_CW;
    float* ppc  = sm + S_PPC;
    float* p1   = sm + S_P1;
    float* p2   = sm + S_P2;

    const int j32 = tid & 31;
    const int g8  = tid >> 5;

    // ---------------- Phase 1: loads ----------------
    for (int idx = tid; idx < 6912; idx += NTHR) {
        int c = idx / 216, tl = idx % 216;
        fs[tl * 36 + c] = x[base + idx];
    }
    for (int idx = tid; idx < 1024; idx += NTHR) {
        int j = idx >> 5, i = idx & 31;
        wq[i * 33 + j] = q_w[idx];
        wk[i * 33 + j] = k_w[idx];
        wv[i * 33 + j] = v_w[idx];
        wm[i * 33 + j] = m_w[idx];
        aA[j * 33 + i] = gA32[idx];
    }
    for (int idx = tid; idx < 576; idx += NTHR) {
        int lo = idx / 24, l = idx % 24;
        pwT[l * 25 + lo] = p_w[idx];
    }
    for (int idx = tid; idx < 376; idx += NTHR) bmx[idx] = gBmixr[idx];
    if (tid < 64) { sWL[tid] = W_logit[tid]; sWC[tid] = W_ctx[tid]; }
    if (tid < 32) {
        bq[tid] = q_b[tid]; bk[tid] = k_b[tid];
        bv[tid] = v_b[tid]; bm[tid] = m_b[tid];
    }
    if (tid < 24) pbf[tid] = p_b[tid];
    __syncthreads();

    // ---------------- Phase 2: per-channel stats (on raw x) ----------------
    {
        int c = tid >> 3, part = tid & 7;
        float s = 0.f, sq = 0.f;
        int tl0 = part * 27;
#pragma unroll 9
        for (int k2 = 0; k2 < 27; ++k2) {
            float v = fs[(tl0 + k2) * 36 + c];
            s += v; sq += v * v;
        }
        psum[c * 8 + part] = s;
        psq [c * 8 + part] = sq;
    }
    __syncthreads();

    // ---------------- Phase 2b: warp-0 scalar chain ----------------
    if (tid < 32) {
        const int c = tid;
        float s = 0.f, sq = 0.f;
#pragma unroll
        for (int p = 0; p < 8; ++p) { s += psum[c * 8 + p]; sq += psq[c * 8 + p]; }
        float pooled = s * (1.f / 216.f);
        float varu = (sq - s * s * (1.f / 216.f)) * (1.f / 215.f);
        float scalec = fmaxf(sqrtf(fmaxf(varu, 0.f)), 1e-3f);

        float mu = pooled;
#pragma unroll
        for (int o = 16; o > 0; o >>= 1) mu += __shfl_xor_sync(0xffffffffu, mu, o);
        mu *= (1.f / 32.f);
        float d = pooled - mu;
        float var = d * d;
#pragma unroll
        for (int o = 16; o > 0; o >>= 1) var += __shfl_xor_sync(0xffffffffu, var, o);
        var *= (1.f / 32.f);
        float pn = d * rsqrtf(var + 1e-5f) * ln_g[c] + ln_b[c];
        vc1[c] = pn; __syncwarp();

        float acc = rp_b1[c];
#pragma unroll
        for (int i = 0; i < 32; ++i) acc += vc1[i] * rp_w1[c * 32 + i];
        vc2[c] = geluf(acc); __syncwarp();

        acc = rp_b2[c];
#pragma unroll
        for (int i = 0; i < 32; ++i) acc += vc2[i] * rp_w2[c * 32 + i];
        vc1[c] = acc; __syncwarp();       // pooled_rule

        acc = mask_b[c];
#pragma unroll
        for (int i = 0; i < 32; ++i) acc += vc1[i] * mask_w[c * 32 + i];
        float M = sigmoidf_(acc);

        acc = val_b1[c];
#pragma unroll
        for (int i = 0; i < 32; ++i) acc += vc1[i] * val_w1[c * 32 + i];
        vc2[c] = geluf(acc); __syncwarp();

        acc = val_b2[c];
#pragma unroll
        for (int i = 0; i < 32; ++i) acc += vc2[i] * val_w2[c * 32 + i];
        float v32 = tanhf(acc) * scalec + pooled;
        float xdo = (1.f - M) * pooled + M * v32;

        float y = xdo;
#pragma unroll
        for (int it = 0; it < 3; ++it) {
            vc3[c] = y; __syncwarp();
            float a2 = xdo;
#pragma unroll
            for (int j = 0; j < 32; ++j) a2 += vc3[j] * aA[c * 33 + j];
            y = a2;
            __syncwarp();
        }
        sdl[c] = sigmoidf_(fuse_gate[0]) * (y - pooled);
    }
    __syncthreads();

    // ---------------- Phase 4: attention, chunks of 3 contexts ----------------
    for (int tc = 0; tc < 3; ++tc) {
        const int rowbase = tc * 72;
        const int crow = g8 * 9;     // this thread's base row within chunk

        // 4a: q/k/v projections for 72 rows, fuse folded in, norm via shfl
        {
            float aq[9], ak[9], av[9];
#pragma unroll
            for (int r = 0; r < 9; ++r) { aq[r] = bq[j32]; ak[r] = bk[j32]; av[r] = bv[j32]; }
#pragma unroll
            for (int i4 = 0; i4 < 8; ++i4) {
                float4 sd4 = *(const float4*)&sdl[i4 * 4];
                float wq0 = wq[(i4*4+0)*33 + j32], wq1 = wq[(i4*4+1)*33 + j32];
                float wq2 = wq[(i4*4+2)*33 + j32], wq3 = wq[(i4*4+3)*33 + j32];
                float wk0 = wk[(i4*4+0)*33 + j32], wk1 = wk[(i4*4+1)*33 + j32];
                float wk2 = wk[(i4*4+2)*33 + j32], wk3 = wk[(i4*4+3)*33 + j32];
                float wv0 = wv[(i4*4+0)*33 + j32], wv1 = wv[(i4*4+1)*33 + j32];
                float wv2 = wv[(i4*4+2)*33 + j32], wv3 = wv[(i4*4+3)*33 + j32];
#pragma unroll
                for (int r = 0; r < 9; ++r) {
                    float4 f4 = *(const float4*)&fs[(rowbase + crow + r) * 36 + i4 * 4];
                    float f0 = f4.x + sd4.x, f1 = f4.y + sd4.y;
                    float f2 = f4.z + sd4.z, f3 = f4.w + sd4.w;
                    aq[r] = fmaf(f0, wq0, aq[r]); aq[r] = fmaf(f1, wq1, aq[r]);
                    aq[r] = fmaf(f2, wq2, aq[r]); aq[r] = fmaf(f3, wq3, aq[r]);
                    ak[r] = fmaf(f0, wk0, ak[r]); ak[r] = fmaf(f1, wk1, ak[r]);
                    ak[r] = fmaf(f2, wk2, ak[r]); ak[r] = fmaf(f3, wk3, ak[r]);
                    av[r] = fmaf(f0, wv0, av[r]); av[r] = fmaf(f1, wv1, av[r]);
                    av[r] = fmaf(f2, wv2, av[r]); av[r] = fmaf(f3, wv3, av[r]);
                }
            }
            // cosine norm per head (channels = lane quads), 0.5/sqrt(HD) in q
#pragma unroll
            for (int r = 0; r < 9; ++r) {
                float n2 = aq[r] * aq[r];
                n2 += __shfl_xor_sync(0xffffffffu, n2, 1);
                n2 += __shfl_xor_sync(0xffffffffu, n2, 2);
                aq[r] *= 0.5f / fmaxf(sqrtf(n2), 1e-12f);
                n2 = ak[r] * ak[r];
                n2 += __shfl_xor_sync(0xffffffffu, n2, 1);
                n2 += __shfl_xor_sync(0xffffffffu, n2, 2);
                ak[r] *= 1.f / fmaxf(sqrtf(n2), 1e-12f);
                n2 = av[r] * av[r];
                n2 += __shfl_xor_sync(0xffffffffu, n2, 1);
                n2 += __shfl_xor_sync(0xffffffffu, n2, 2);
                av[r] *= 1.f / fmaxf(sqrtf(n2), 1e-12f);
                q3[(crow + r) * 36 + j32] = aq[r];
                k3[(crow + r) * 36 + j32] = ak[r];
                v3[(crow + r) * 36 + j32] = av[r];
            }
        }
        __syncthreads();

        for (int t3 = 0; t3 < 3; ++t3) {
            const int ro = t3 * 24;

            // 4c: logits + W_logit mix (bias deferred to softmax)
            if (tid < 192) {
                const int i = tid >> 3, jg = tid & 7;
                float raw[3][8];
#pragma unroll
                for (int h = 0; h < 8; ++h) {
                    float4 qh = *(const float4*)&q3[(ro + i) * 36 + h * 4];
#pragma unroll
                    for (int r = 0; r < 3; ++r) {
                        float4 kv = *(const float4*)&k3[(ro + jg * 3 + r) * 36 + h * 4];
                        raw[r][h] = qh.x*kv.x + qh.y*kv.y + qh.z*kv.z + qh.w*kv.w;
                    }
                }
#pragma unroll
                for (int Ho = 0; Ho < 8; ++Ho) {
                    float wl[8];
#pragma unroll
                    for (int h = 0; h < 8; ++h) wl[h] = sWL[h * 8 + Ho];
#pragma unroll
                    for (int r = 0; r < 3; ++r) {
                        float acc = 0.f;
#pragma unroll
                        for (int h = 0; h < 8; ++h) acc = fmaf(raw[r][h], wl[h], acc);
                        smx[Ho * 676 + i * 28 + jg * 3 + r] = acc;
                    }
                }
            }
            __syncthreads();

            // 4d: softmax over j with rel-pos bias (vectorized row access)
            if (tid < 192) {
                const int Ho = tid / 24, i = tid % 24;
                float* row = &smx[Ho * 676 + i * 28];
                const float* brow = &bmx[Ho * 47 + i + 23];
                float e[24];
                {
                    const float4* rp = (const float4*)row;
#pragma unroll
                    for (int q4 = 0; q4 < 6; ++q4) {
                        float4 v4 = rp[q4];
                        e[q4*4+0] = v4.x; e[q4*4+1] = v4.y;
                        e[q4*4+2] = v4.z; e[q4*4+3] = v4.w;
                    }
                }
                float mx = -1e30f;
#pragma unroll
                for (int j = 0; j < 24; ++j) {
                    e[j] += brow[-j];
                    mx = fmaxf(mx, e[j]);
                }
                float ssum = 0.f;
#pragma unroll
                for (int j = 0; j < 24; ++j) { e[j] = __expf(e[j] - mx); ssum += e[j]; }
                float inv = 1.f / ssum;
                float4* wp = (float4*)row;
#pragma unroll
                for (int q4 = 0; q4 < 6; ++q4) {
                    float4 v4;
                    v4.x = e[q4*4+0] * inv; v4.y = e[q4*4+1] * inv;
                    v4.z = e[q4*4+2] * inv; v4.w = e[q4*4+3] * inv;
                    wp[q4] = v4;
                }
            }
            __syncthreads();

            // 4e: W_ctx mix, in place
            if (tid < 192) {
                const int i = tid >> 3, jg = tid & 7;
                float sv[3][8];
#pragma unroll
                for (int h = 0; h < 8; ++h)
#pragma unroll
                    for (int r = 0; r < 3; ++r)
                        sv[r][h] = smx[h * 676 + i * 28 + jg * 3 + r];
#pragma unroll
                for (int Ho = 0; Ho < 8; ++Ho) {
                    float wc[8];
#pragma unroll
                    for (int h = 0; h < 8; ++h) wc[h] = sWC[h * 8 + Ho];
#pragma unroll
                    for (int r = 0; r < 3; ++r) {
                        float acc = 0.f;
#pragma unroll
                        for (int h = 0; h < 8; ++h) acc = fmaf(sv[r][h], wc[h], acc);
                        smx[Ho * 676 + i * 28 + jg * 3 + r] = acc;
                    }
                }
            }
            __syncthreads();

            // 4f: AV -> write att back into q3 rows of this t3
            {
                const int h = j32 >> 2;
                float acc[3] = {0.f, 0.f, 0.f};
#pragma unroll
                for (int j4 = 0; j4 < 6; ++j4) {
                    float s4[3][4];
#pragma unroll
                    for (int r = 0; r < 3; ++r) {
                        float4 t = *(const float4*)&smx[h * 676 + (g8 * 3 + r) * 28 + j4 * 4];
                        s4[r][0] = t.x; s4[r][1] = t.y; s4[r][2] = t.z; s4[r][3] = t.w;
                    }
#pragma unroll
                    for (int s = 0; s < 4; ++s) {
                        float vv = v3[(ro + j4 * 4 + s) * 36 + j32];
#pragma unroll
                        for (int r = 0; r < 3; ++r)
                            acc[r] = fmaf(s4[r][s], vv, acc[r]);
                    }
                }
#pragma unroll
                for (int r = 0; r < 3; ++r)
                    q3[(ro + g8 * 3 + r) * 36 + j32] = acc[r];
            }
            __syncthreads();
        }

        // 4g: output projection for the whole chunk, overwrite fs rows
        {
            float am[9];
#pragma unroll
            for (int r = 0; r < 9; ++r) am[r] = bm[j32];
#pragma unroll
            for (int i4 = 0; i4 < 8; ++i4) {
                float wm0 = wm[(i4*4+0)*33 + j32], wm1 = wm[(i4*4+1)*33 + j32];
                float wm2 = wm[(i4*4+2)*33 + j32], wm3 = wm[(i4*4+3)*33 + j32];
#pragma unroll
                for (int r = 0; r < 9; ++r) {
                    float4 a4 = *(const float4*)&q3[(crow + r) * 36 + i4 * 4];
                    am[r] = fmaf(a4.x, wm0, am[r]); am[r] = fmaf(a4.y, wm1, am[r]);
                    am[r] = fmaf(a4.z, wm2, am[r]); am[r] = fmaf(a4.w, wm3, am[r]);
                }
            }
#pragma unroll
            for (int r = 0; r < 9; ++r)
                fs[(rowbase + crow + r) * 36 + j32] = am[r];
        }
        __syncthreads();
    }

    // ---------------- Phase 5: conv over contexts ----------------
    for (int idx = tid; idx < 9216; idx += NTHR) {
        int o = idx / 288, rem = idx % 288;   // rem = i*9 + kt
        cw[rem * 33 + o] = conv_w[idx];
    }
    for (int idx = tid; idx < 768; idx += NTHR) {
        int o = idx / 24, l = idx % 24;
        ppc[o * 25 + l] = gPPC[idx];
    }
    __syncthreads();
    if (g8 < 4) {
        const int lbase = g8 * 6;
        float acc[6];
#pragma unroll
        for (int r = 0; r < 6; ++r) acc[r] = ppc[j32 * 25 + lbase + r];
#pragma unroll
        for (int i4 = 0; i4 < 8; ++i4) {
#pragma unroll
            for (int kt = 0; kt < 8; ++kt) {
                float w0 = cw[((i4*4+0)*9 + kt)*33 + j32];
                float w1 = cw[((i4*4+1)*9 + kt)*33 + j32];
                float w2 = cw[((i4*4+2)*9 + kt)*33 + j32];
                float w3 = cw[((i4*4+3)*9 + kt)*33 + j32];
#pragma unroll
                for (int r = 0; r < 6; ++r) {
                    float4 f4 = *(const float4*)&fs[(kt * 24 + lbase + r) * 36 + i4 * 4];
                    acc[r] = fmaf(f4.x, w0, acc[r]);
                    acc[r] = fmaf(f4.y, w1, acc[r]);
                    acc[r] = fmaf(f4.z, w2, acc[r]);
                    acc[r] = fmaf(f4.w, w3, acc[r]);
                }
            }
        }
#pragma unroll
        for (int r = 0; r < 6; ++r)
            p1[j32 * 25 + lbase + r] = fmaxf(acc[r], 0.f);
    }
    __syncthreads();

    // ---------------- Phase 6: token linear ----------------
    for (int idx = tid; idx < 768; idx += NTHR) {
        int o = idx / 24, lo = idx % 24;
        float acc = pbf[lo];
#pragma unroll
        for (int l = 0; l < 24; ++l)
            acc = fmaf(p1[o * 25 + l], pwT[l * 25 + lo], acc);
        p2[o * 25 + lo] = acc;
    }
    __syncthreads();

    // ---------------- Phase 7: output ----------------
    for (int idx = tid; idx < 6912; idx += NTHR) {
        int c = idx / 216, tl = idx % 216;
        float v = fs[tl * 36 + c];
        if (tl >= 192) v -= p2[c * 25 + (tl - 192)];
        out[base + idx] = v;
    }
}

extern "C" void kernel_launch(void* const* d_in, const int* in_sizes, int n_in,
                              void* d_out, int out_size) {
    const float* x        = (const float*)d_in[0];
    const float* ln_g     = (const float*)d_in[1];
    const float* ln_b     = (const float*)d_in[2];
    const float* rp_w1    = (const float*)d_in[3];
    const float* rp_b1    = (const float*)d_in[4];
    const float* rp_w2    = (const float*)d_in[5];
    const float* rp_b2    = (const float*)d_in[6];
    const float* W_causal = (const float*)d_in[7];
    const float* mask_w   = (const float*)d_in[8];
    const float* mask_b   = (const float*)d_in[9];
    const float* val_w1   = (const float*)d_in[10];
    const float* val_b1   = (const float*)d_in[11];
    const float* val_w2   = (const float*)d_in[12];
    const float* val_b2   = (const float*)d_in[13];
    const float* fuse_g   = (const float*)d_in[14];
    const float* q_w      = (const float*)d_in[15];
    const float* q_b      = (const float*)d_in[16];
    const float* k_w      = (const float*)d_in[17];
    const float* k_b      = (const float*)d_in[18];
    const float* v_w      = (const float*)d_in[19];
    const float* v_b      = (const float*)d_in[20];
    const float* m_w      = (const float*)d_in[21];
    const float* m_b      = (const float*)d_in[22];
    const float* W_logit  = (const float*)d_in[23];
    const float* W_ctx    = (const float*)d_in[24];
    const float* rpb      = (const float*)d_in[25];
    const float* pre_p    = (const float*)d_in[26];
    const float* conv_w   = (const float*)d_in[27];
    const float* conv_b   = (const float*)d_in[28];
    const float* p_w      = (const float*)d_in[29];
    const float* p_b      = (const float*)d_in[30];
    float* out = (float*)d_out;

    const int smem_bytes = S_TOTAL * 4;
    cudaFuncSetAttribute(prb_kernel, cudaFuncAttributeMaxDynamicSharedMemorySize,
                         smem_bytes);

    prb_precompute<<<1, 256>>>(W_causal, W_logit, rpb, conv_w, conv_b, pre_p);

    int B = in_sizes[0] / 6912;
    prb_kernel<<<B, NTHR, smem_bytes>>>(
        x, ln_g, ln_b, rp_w1, rp_b1, rp_w2, rp_b2,
        mask_w, mask_b, val_w1, val_b1, val_w2, val_b2, fuse_g,
        q_w, q_b, k_w, k_b, v_w, v_b, m_w, m_b,
        W_logit, W_ctx, conv_w, p_w, p_b, out);
}